// round 16
// baseline (speedup 1.0000x reference)
#include <cuda_runtime.h>
#include <cuda_bf16.h>
#include <cstdint>
#include <math.h>

// Problem constants
#define BB 2
#define SS 2048
#define DD 1024
#define HH 16
#define DKK 64

#define OUT_ELEMS (BB * SS * DD)                 // 4,194,304
#define NELEM ((size_t)BB * SS * DD)             // 4M

// ---------------------------------------------------------------------------
// Scratch (__device__ globals — no allocation allowed)
// ---------------------------------------------------------------------------
__device__ __nv_bfloat16 g_qhi[NELEM];
__device__ __nv_bfloat16 g_qlo[NELEM];
__device__ __nv_bfloat16 g_khi[NELEM];
__device__ __nv_bfloat16 g_klo[NELEM];
__device__ __nv_bfloat16 g_vhi[NELEM];    // head-major [bh][s][d]
__device__ __nv_bfloat16 g_vlo[NELEM];
__device__ __nv_bfloat16 g_vthi[NELEM];   // transposed [bh][d][s]
__device__ __nv_bfloat16 g_vtlo[NELEM];
__device__ __nv_bfloat16 g_chi[NELEM];
__device__ __nv_bfloat16 g_clo[NELEM];
__device__ __nv_bfloat16 g_Ahi[3 * NELEM];
__device__ __nv_bfloat16 g_Alo[3 * NELEM];
__device__ __nv_bfloat16 g_Bhi[4 * (size_t)DD * DD];
__device__ __nv_bfloat16 g_Blo[4 * (size_t)DD * DD];

// ---------------------------------------------------------------------------
// PTX helpers
// ---------------------------------------------------------------------------
__device__ __forceinline__ uint32_t smem_u32(const void* p) {
    uint32_t a;
    asm("{ .reg .u64 t; cvta.to.shared.u64 t, %1; cvt.u32.u64 %0, t; }" : "=r"(a) : "l"(p));
    return a;
}
__device__ __forceinline__ void cp_async16(uint32_t dst, const void* src) {
    asm volatile("cp.async.cg.shared.global [%0], [%1], 16;\n" :: "r"(dst), "l"(src) : "memory");
}
#define CP_COMMIT() asm volatile("cp.async.commit_group;\n" ::: "memory")
#define CP_WAIT0()  asm volatile("cp.async.wait_group 0;\n" ::: "memory")
#define CP_WAIT1()  asm volatile("cp.async.wait_group 1;\n" ::: "memory")
#define CP_WAIT2()  asm volatile("cp.async.wait_group 2;\n" ::: "memory")
#define CP_WAIT3()  asm volatile("cp.async.wait_group 3;\n" ::: "memory")

__device__ __forceinline__ void ldsm_x4(uint32_t r[4], uint32_t addr) {
    asm volatile("ldmatrix.sync.aligned.m8n8.x4.shared.b16 {%0,%1,%2,%3}, [%4];"
        : "=r"(r[0]), "=r"(r[1]), "=r"(r[2]), "=r"(r[3]) : "r"(addr));
}
__device__ __forceinline__ void mma16816(float d[4], const uint32_t a[4], const uint32_t b[2]) {
    asm volatile(
        "mma.sync.aligned.m16n8k16.row.col.f32.bf16.bf16.f32 "
        "{%0,%1,%2,%3},{%4,%5,%6,%7},{%8,%9},{%0,%1,%2,%3};"
        : "+f"(d[0]), "+f"(d[1]), "+f"(d[2]), "+f"(d[3])
        : "r"(a[0]), "r"(a[1]), "r"(a[2]), "r"(a[3]), "r"(b[0]), "r"(b[1]));
}
__device__ __forceinline__ uint32_t pack2bf(float a, float b) {
    __nv_bfloat162 t = __floats2bfloat162_rn(a, b);
    return *reinterpret_cast<uint32_t*>(&t);
}
__device__ __forceinline__ uint32_t packhalves(__nv_bfloat16 a, __nv_bfloat16 b) {
    __nv_bfloat162 t; t.x = a; t.y = b;
    return *reinterpret_cast<uint32_t*>(&t);
}
__device__ __forceinline__ void st_cs_f2(float* p, float a, float b) {
    asm volatile("st.global.cs.v2.f32 [%0], {%1, %2};" :: "l"(p), "f"(a), "f"(b) : "memory");
}

// ---------------------------------------------------------------------------
// Batched fp32 -> bf16 hi/lo conversion: Q_in, K_in, V_in in one launch.
// ---------------------------------------------------------------------------
__global__ __launch_bounds__(256) void conv_qkv_kernel(
    const float* __restrict__ Q_in, const float* __restrict__ K_in,
    const float* __restrict__ V_in,
    __nv_bfloat16* __restrict__ hi, __nv_bfloat16* __restrict__ lo)
{
    const int nblk = (int)(NELEM / 256);
    int sel = blockIdx.x / nblk;
    int off = (blockIdx.x - sel * nblk) * 256 + threadIdx.x;
    const float* src = (sel == 0) ? Q_in : (sel == 1) ? K_in : V_in;
    float x = src[off];
    size_t o = (size_t)sel * NELEM + off;
    __nv_bfloat16 h = __float2bfloat16(x);
    hi[o] = h;
    lo[o] = __float2bfloat16(x - __bfloat162float(h));
}

// All 4 weights W[K,N] -> Wt hi/lo [N][K], smem-tiled transpose (coalesced).
__global__ __launch_bounds__(256) void convT_all_kernel(
    const float* __restrict__ Wq, const float* __restrict__ Wk,
    const float* __restrict__ Wv, const float* __restrict__ Wo,
    __nv_bfloat16* __restrict__ hi, __nv_bfloat16* __restrict__ lo)
{
    __shared__ float ts[64][65];
    const int tpw = (DD / 64) * (DD / 64);   // 256 tiles per weight
    int sel = blockIdx.x / tpw;
    int t = blockIdx.x - sel * tpw;
    int k0 = (t >> 4) * 64;
    int n0 = (t & 15) * 64;
    const float* W = (sel == 0) ? Wq : (sel == 1) ? Wk : (sel == 2) ? Wv : Wo;
    const int tid = threadIdx.x;

#pragma unroll
    for (int it = 0; it < 16; it++) {
        int idx = tid + it * 256;
        int kr = idx >> 6;
        int nc = idx & 63;
        ts[kr][nc] = W[(size_t)(k0 + kr) * 1024 + n0 + nc];
    }
    __syncthreads();
    size_t base = (size_t)sel * DD * DD;
#pragma unroll
    for (int it = 0; it < 16; it++) {
        int idx = tid + it * 256;
        int nr = idx >> 6;
        int kc = idx & 63;
        float x = ts[kc][nr];
        __nv_bfloat16 h = __float2bfloat16(x);
        size_t o = base + (size_t)(n0 + nr) * 1024 + k0 + kc;
        hi[o] = h;
        lo[o] = __float2bfloat16(x - __bfloat162float(h));
    }
}

// ---------------------------------------------------------------------------
// V transpose: [bh][s][d] -> [bh][d][s], 64x64 tiles, hi+lo in one pass.
// ---------------------------------------------------------------------------
__global__ __launch_bounds__(256) void vtrans_kernel(
    const __nv_bfloat16* __restrict__ shi, const __nv_bfloat16* __restrict__ slo,
    __nv_bfloat16* __restrict__ dhi, __nv_bfloat16* __restrict__ dlo)
{
    __shared__ __nv_bfloat16 th[64][66];
    __shared__ __nv_bfloat16 tl[64][66];
    const int tid = threadIdx.x;
    const int bh = blockIdx.y;
    const int s0 = blockIdx.x * 64;

#pragma unroll
    for (int it = 0; it < 2; it++) {
        int idx = tid + it * 256;
        int r = idx >> 3;
        int sg = idx & 7;
        size_t g = ((size_t)bh * SS + s0 + r) * DKK + sg * 8;
        uint4 vh = *(const uint4*)&shi[g];
        uint4 vl = *(const uint4*)&slo[g];
        uint32_t* ph = (uint32_t*)&th[r][sg * 8];
        ph[0] = vh.x; ph[1] = vh.y; ph[2] = vh.z; ph[3] = vh.w;
        uint32_t* pl = (uint32_t*)&tl[r][sg * 8];
        pl[0] = vl.x; pl[1] = vl.y; pl[2] = vl.z; pl[3] = vl.w;
    }
    __syncthreads();

#pragma unroll
    for (int it = 0; it < 2; it++) {
        int idx = tid + it * 256;
        int d = idx >> 3;
        int sg = idx & 7;
        __nv_bfloat16 bh8[8], bl8[8];
#pragma unroll
        for (int k = 0; k < 8; k++) {
            bh8[k] = th[sg * 8 + k][d];
            bl8[k] = tl[sg * 8 + k][d];
        }
        size_t g = ((size_t)bh * DKK + d) * SS + s0 + sg * 8;
        *(uint4*)&dhi[g] = *(uint4*)bh8;
        *(uint4*)&dlo[g] = *(uint4*)bl8;
    }
}

// ---------------------------------------------------------------------------
// mma.sync GEMM (256 threads, 2 CTAs/SM): C = A @ B^T + bias, bf16x3 split.
// Tile 64(M) x 128(N), BK=64 double-buffered. 8 warps = 2m x 4n groups.
// ---------------------------------------------------------------------------
#define GM_TA 9216               // 64 rows x 144B
#define GM_TB 18432              // 128 rows x 144B
#define GM_BUF  (2 * GM_TA + 2 * GM_TB)    // 55296
#define GM_SMEM_BYTES (2 * GM_BUF)         // 110592

struct GemmOuts {
    const float* bias[3];
    __nv_bfloat16* hi[3];
    __nv_bfloat16* lo[3];
    float* cf[3];
};

template <int MODE>
__global__ __launch_bounds__(256, 2) void gemm_mma_kernel(
    const __nv_bfloat16* __restrict__ AhiB, const __nv_bfloat16* __restrict__ AloB,
    const __nv_bfloat16* __restrict__ BhiB, const __nv_bfloat16* __restrict__ BloB,
    GemmOuts P)
{
    extern __shared__ char smem[];
    __shared__ float sbias[128];
    const uint32_t sbase = smem_u32(smem);

    const int z = blockIdx.z;
    const __nv_bfloat16* Ahi = AhiB + (size_t)z * NELEM;
    const __nv_bfloat16* Alo = AloB + (size_t)z * NELEM;
    const __nv_bfloat16* Bhi = BhiB + (size_t)z * DD * DD;
    const __nv_bfloat16* Blo = BloB + (size_t)z * DD * DD;

    const int tid = threadIdx.x;
    const int wid = tid >> 5;
    const int lane = tid & 31;
    const int rowBase = blockIdx.y * 64;
    const int colBase = blockIdx.x * 128;

    if (tid < 128) sbias[tid] = P.bias[z][colBase + tid];

    const int wm = (wid >> 2) * 32;
    const int wn = (wid & 3) * 32;

    float acc[2][4][4];
#pragma unroll
    for (int i = 0; i < 2; i++)
#pragma unroll
        for (int j = 0; j < 4; j++)
#pragma unroll
            for (int e = 0; e < 4; e++) acc[i][j][e] = 0.0f;

    auto load_chunk = [&](int c) {
        const int buf = c & 1;
        const int k0 = c * 64;
        const uint32_t sb = sbase + buf * GM_BUF;
#pragma unroll
        for (int it = 0; it < 2; it++) {
            int idx = tid + it * 256;
            int r = idx >> 3;
            int sg = idx & 7;
            uint32_t so = (uint32_t)(r * 144 + sg * 16);
            size_t ga = (size_t)(rowBase + r) * 1024 + k0 + sg * 8;
            cp_async16(sb + so, Ahi + ga);
            cp_async16(sb + GM_TA + so, Alo + ga);
        }
#pragma unroll
        for (int it = 0; it < 4; it++) {
            int idx = tid + it * 256;
            int r = idx >> 3;
            int sg = idx & 7;
            uint32_t so = (uint32_t)(r * 144 + sg * 16);
            size_t gb = (size_t)(colBase + r) * 1024 + k0 + sg * 8;
            cp_async16(sb + 2 * GM_TA + so, Bhi + gb);
            cp_async16(sb + 2 * GM_TA + GM_TB + so, Blo + gb);
        }
        CP_COMMIT();
    };

    const int arow = lane & 15;
    const int akk0 = (lane >> 4) << 3;
    const int brow = (lane & 7) + ((lane & 16) ? 8 : 0);
    const int bkk0 = (lane & 8) ? 8 : 0;

    load_chunk(0);
    for (int c = 0; c < 16; c++) {
        if (c < 15) load_chunk(c + 1);
        if (c < 15) { CP_WAIT1(); } else { CP_WAIT0(); }
        __syncthreads();

        const uint32_t sb = sbase + (c & 1) * GM_BUF;
#pragma unroll
        for (int ks = 0; ks < 4; ks++) {
            const int k0s = ks * 16;
            uint32_t ahi[2][4], alo[2][4];
#pragma unroll
            for (int mt = 0; mt < 2; mt++) {
                uint32_t ad = sb + (uint32_t)((wm + mt * 16 + arow) * 144 + (k0s + akk0) * 2);
                ldsm_x4(ahi[mt], ad);
                ldsm_x4(alo[mt], ad + GM_TA);
            }
            uint32_t bhiF[2][4], bloF[2][4];
#pragma unroll
            for (int nt2 = 0; nt2 < 2; nt2++) {
                uint32_t bd = sb + 2 * GM_TA +
                    (uint32_t)((wn + nt2 * 16 + brow) * 144 + (k0s + bkk0) * 2);
                ldsm_x4(bhiF[nt2], bd);
                ldsm_x4(bloF[nt2], bd + GM_TB);
            }
#pragma unroll
            for (int mt = 0; mt < 2; mt++)
#pragma unroll
                for (int nt = 0; nt < 4; nt++) {
                    const uint32_t* bh = &bhiF[nt >> 1][(nt & 1) * 2];
                    const uint32_t* bl = &bloF[nt >> 1][(nt & 1) * 2];
                    mma16816(acc[mt][nt], ahi[mt], bh);
                    mma16816(acc[mt][nt], ahi[mt], bl);
                    mma16816(acc[mt][nt], alo[mt], bh);
                }
        }
        __syncthreads();
    }

#pragma unroll
    for (int mt = 0; mt < 2; mt++)
#pragma unroll
        for (int nt = 0; nt < 4; nt++)
#pragma unroll
            for (int half = 0; half < 2; half++) {
                int row = rowBase + wm + mt * 16 + (lane >> 2) + half * 8;
                int col = colBase + wn + nt * 8 + (lane & 3) * 2;
                float x0 = acc[mt][nt][half * 2 + 0] + sbias[col - colBase];
                float x1 = acc[mt][nt][half * 2 + 1] + sbias[col - colBase + 1];
                if (MODE == 0) {
                    *(float2*)&P.cf[z][(size_t)row * 1024 + col] = make_float2(x0, x1);
                } else {
                    int b = row >> 11, s = row & 2047;
                    int h = col >> 6, d = col & 63;
                    __nv_bfloat16 h0 = __float2bfloat16(x0);
                    __nv_bfloat16 h1 = __float2bfloat16(x1);
                    __nv_bfloat16 l0 = __float2bfloat16(x0 - __bfloat162float(h0));
                    __nv_bfloat16 l1 = __float2bfloat16(x1 - __bfloat162float(h1));
                    size_t idx = (((size_t)b * HH + h) * SS + s) * DKK + d;
                    *(uint32_t*)&P.hi[z][idx] = packhalves(h0, h1);
                    *(uint32_t*)&P.lo[z][idx] = packhalves(l0, l1);
                }
            }
}

// ---------------------------------------------------------------------------
// Fused attention (256 threads, 2 CTAs/SM), P-in-register AV, MAX-based
// softmax (R14 numerics). Pass 1: hi-only QK, j-tile 128, 4-deep K ring,
// hoisted Q fragments, ONE sync/iter. Pass 2: exact 3-mma QK + softmax +
// streaming attn write + AV (j-tile 64).
// ---------------------------------------------------------------------------
#define FA_ROW 144                      // 64*2 data + 16 pad
#define FA_ARR 9216                     // 64 * 144
#define FA_KBASE (2 * FA_ARR)           // 18432
#define FA_VBASE (FA_KBASE + 4 * FA_ARR)// 55296
#define FA_SMEM  (FA_VBASE + 4 * FA_ARR)// 92160
#define NJT (SS / 64)                   // 32 (pass 2)
#define NJT1 (SS / 128)                 // 16 (pass 1)
#define K1_TILE 18432                   // 128 rows x 144B (hi only)

__global__ __launch_bounds__(256, 2) void attn_fused_kernel(
    const __nv_bfloat16* __restrict__ qhi, const __nv_bfloat16* __restrict__ qlo,
    const __nv_bfloat16* __restrict__ khi, const __nv_bfloat16* __restrict__ klo,
    const __nv_bfloat16* __restrict__ vhi, const __nv_bfloat16* __restrict__ vlo,
    float* __restrict__ attn,
    __nv_bfloat16* __restrict__ chi, __nv_bfloat16* __restrict__ clo)
{
    extern __shared__ char smem[];
    __shared__ float sm_m[64][2];
    __shared__ float sm_s[64][2];
    __shared__ float smax[64], sinv[64];
    const uint32_t sbase = smem_u32(smem);

    const int tid = threadIdx.x;
    const int wid = tid >> 5;
    const int lane = tid & 31;
    const int bh = blockIdx.y;
    const int b = bh >> 4;
    const int h = bh & 15;
    const int i0 = blockIdx.x * 64;

    const int arow = lane & 15;
    const int akk0 = (lane >> 4) << 3;
    const int brow = (lane & 7) + ((lane & 16) ? 8 : 0);
    const int bkk0 = (lane & 8) ? 8 : 0;

    const int mg = wid >> 1;
    const int jg = wid & 1;
    const int wmq = mg * 16;
    const int wnq = jg * 32;    // pass-2 j-slice
    const int wnq1 = jg * 64;   // pass-1 j-slice

    auto load_k = [&](int jt) {
        const uint32_t kb = sbase + FA_KBASE + (uint32_t)(jt & 1) * (2 * FA_ARR);
        const int j0 = jt * 64;
#pragma unroll
        for (int it = 0; it < 2; it++) {
            int idx = tid + it * 256;
            int r = idx >> 3;
            int sg = idx & 7;
            uint32_t so = (uint32_t)(r * FA_ROW + sg * 16);
            size_t gk = ((size_t)bh * SS + j0 + r) * DKK + sg * 8;
            cp_async16(kb + so, khi + gk);
            cp_async16(kb + FA_ARR + so, klo + gk);
        }
        CP_COMMIT();
    };
    auto load_k1 = [&](int jt) {
        const uint32_t kb = sbase + FA_KBASE + (uint32_t)(jt & 3) * K1_TILE;
        const int j0 = jt * 128;
#pragma unroll
        for (int it = 0; it < 4; it++) {
            int idx = tid + it * 256;
            int r = idx >> 3;
            int sg = idx & 7;
            uint32_t so = (uint32_t)(r * FA_ROW + sg * 16);
            size_t gk = ((size_t)bh * SS + j0 + r) * DKK + sg * 8;
            cp_async16(kb + so, khi + gk);
        }
        CP_COMMIT();
    };
    auto load_v = [&](int jt) {
        const uint32_t vb = sbase + FA_VBASE + (uint32_t)(jt & 1) * (2 * FA_ARR);
        const int j0 = jt * 64;
#pragma unroll
        for (int it = 0; it < 2; it++) {
            int idx = tid + it * 256;
            int d = idx >> 3;
            int sg = idx & 7;
            uint32_t so = (uint32_t)(d * FA_ROW + sg * 16);
            size_t g = ((size_t)bh * DKK + d) * SS + j0 + sg * 8;
            cp_async16(vb + so, vhi + g);
            cp_async16(vb + FA_ARR + so, vlo + g);
        }
        CP_COMMIT();
    };

    // Prologue: q (hi+lo) shares commit with K1(0); then K1(1), K1(2)
#pragma unroll
    for (int it = 0; it < 2; it++) {
        int idx = tid + it * 256;
        int r = idx >> 3;
        int sg = idx & 7;
        uint32_t so = (uint32_t)(r * FA_ROW + sg * 16);
        size_t gq = ((size_t)bh * SS + i0 + r) * DKK + sg * 8;
        cp_async16(sbase + so, qhi + gq);
        cp_async16(sbase + FA_ARR + so, qlo + gq);
    }
    load_k1(0);
    load_k1(1);
    load_k1(2);

    float mrun[2], srun[2];
#pragma unroll
    for (int i = 0; i < 2; i++) { mrun[i] = -1e30f; srun[i] = 0.0f; }

    // ---------------- Pass 1: hi-only QK, j128, ring-4, 1 sync/iter ---------
    uint32_t qfrag[4][4];
    int qld = 0;
    for (int jt = 0; jt < NJT1; jt++) {
        if (jt + 3 < NJT1) load_k1(jt + 3);
        int rem = NJT1 - 1 - jt;
        if (rem >= 3)      { CP_WAIT3(); }
        else if (rem == 2) { CP_WAIT2(); }
        else if (rem == 1) { CP_WAIT1(); }
        else               { CP_WAIT0(); }
        __syncthreads();

        if (!qld) {
            qld = 1;
#pragma unroll
            for (int ks = 0; ks < 4; ks++) {
                uint32_t ad = sbase + (uint32_t)((wmq + arow) * FA_ROW + (ks * 16 + akk0) * 2);
                ldsm_x4(qfrag[ks], ad);
            }
        }

        const uint32_t kb = sbase + FA_KBASE + (uint32_t)(jt & 3) * K1_TILE;

        float acc[8][4];
#pragma unroll
        for (int j = 0; j < 8; j++)
#pragma unroll
            for (int e = 0; e < 4; e++) acc[j][e] = 0.0f;

#pragma unroll
        for (int ks = 0; ks < 4; ks++) {
            uint32_t bF[4][4];
#pragma unroll
            for (int nt2 = 0; nt2 < 4; nt2++) {
                uint32_t bd = kb + (uint32_t)((wnq1 + nt2 * 16 + brow) * FA_ROW + (ks * 16 + bkk0) * 2);
                ldsm_x4(bF[nt2], bd);
            }
#pragma unroll
            for (int nt = 0; nt < 8; nt++)
                mma16816(acc[nt], qfrag[ks], &bF[nt >> 1][(nt & 1) * 2]);
        }

        // max-based online stats (R14 numerics)
#pragma unroll
        for (int half = 0; half < 2; half++) {
            float tm = -1e30f;
#pragma unroll
            for (int nt = 0; nt < 8; nt++)
                tm = fmaxf(tm, fmaxf(acc[nt][half * 2 + 0], acc[nt][half * 2 + 1]));
            tm *= 0.125f;
            tm = fmaxf(tm, __shfl_xor_sync(0xFFFFFFFFu, tm, 1));
            tm = fmaxf(tm, __shfl_xor_sync(0xFFFFFFFFu, tm, 2));
            float nm = fmaxf(mrun[half], tm);
            float ps = 0.0f;
#pragma unroll
            for (int nt = 0; nt < 8; nt++) {
                ps += __expf(acc[nt][half * 2 + 0] * 0.125f - nm);
                ps += __expf(acc[nt][half * 2 + 1] * 0.125f - nm);
            }
            ps += __shfl_xor_sync(0xFFFFFFFFu, ps, 1);
            ps += __shfl_xor_sync(0xFFFFFFFFu, ps, 2);
            srun[half] = srun[half] * __expf(mrun[half] - nm) + ps;
            mrun[half] = nm;
        }
        // no end-of-iter sync: ring-4 guarantees no overwrite hazard
    }
    __syncthreads();   // all pass-1 buffer reads complete

    // Merge stats across the 2 jg warp columns
    if ((lane & 3) == 0) {
#pragma unroll
        for (int half = 0; half < 2; half++) {
            int rl = wmq + (lane >> 2) + half * 8;
            sm_m[rl][jg] = mrun[half];
            sm_s[rl][jg] = srun[half];
        }
    }
    __syncthreads();
    // Pass-2 prologue loads (safe: all pass-1 reads done)
    load_k(0);
    load_v(0);
    if (tid < 64) {
        float m0 = sm_m[tid][0], m1 = sm_m[tid][1];
        float M = fmaxf(m0, m1);
        float s = sm_s[tid][0] * __expf(m0 - M) + sm_s[tid][1] * __expf(m1 - M);
        smax[tid] = M;
        sinv[tid] = 1.0f / s;
    }

    float accv[8][4];
#pragma unroll
    for (int j = 0; j < 8; j++)
#pragma unroll
        for (int e = 0; e < 4; e++) accv[j][e] = 0.0f;

    // ---------------- Pass 2: exact QK + softmax + attn write + AV ----------
    for (int jt = 0; jt < NJT; jt++) {
        if (jt < NJT - 1) { load_v(jt + 1); load_k(jt + 1); CP_WAIT2(); }
        else { CP_WAIT0(); }
        __syncthreads();   // K(jt), V(jt) ready; smax/sinv visible (first iter)

        const uint32_t kb = sbase + FA_KBASE + (uint32_t)(jt & 1) * (2 * FA_ARR);
        const uint32_t vb = sbase + FA_VBASE + (uint32_t)(jt & 1) * (2 * FA_ARR);
        const int j0 = jt * 64;

        float acc[4][4];
#pragma unroll
        for (int j = 0; j < 4; j++)
#pragma unroll
            for (int e = 0; e < 4; e++) acc[j][e] = 0.0f;

#pragma unroll
        for (int ks = 0; ks < 4; ks++) {
            uint32_t qh[4], ql[4];
            {
                uint32_t ad = sbase + (uint32_t)((wmq + arow) * FA_ROW + (ks * 16 + akk0) * 2);
                ldsm_x4(qh, ad);
                ldsm_x4(ql, ad + FA_ARR);
            }
            uint32_t bhiF[2][4], bloF[2][4];
#pragma unroll
            for (int nt2 = 0; nt2 < 2; nt2++) {
                uint32_t bd = kb + (uint32_t)((wnq + nt2 * 16 + brow) * FA_ROW + (ks * 16 + bkk0) * 2);
                ldsm_x4(bhiF[nt2], bd);
                ldsm_x4(bloF[nt2], bd + FA_ARR);
            }
#pragma unroll
            for (int nt = 0; nt < 4; nt++) {
                const uint32_t* bhp = &bhiF[nt >> 1][(nt & 1) * 2];
                const uint32_t* blp = &bloF[nt >> 1][(nt & 1) * 2];
                mma16816(acc[nt], qh, bhp);
                mma16816(acc[nt], qh, blp);
                mma16816(acc[nt], ql, bhp);
            }
        }

        // softmax in-register: P = exp(s*0.125 - M) * inv; streaming attn write
        uint32_t Phi[2][4], Plo[2][4];
#pragma unroll
        for (int half = 0; half < 2; half++) {
            int row_l = wmq + (lane >> 2) + half * 8;
            float M = smax[row_l], inv = sinv[row_l];
#pragma unroll
            for (int nt = 0; nt < 4; nt++) {
                float p0 = __expf(acc[nt][half * 2 + 0] * 0.125f - M) * inv;
                float p1 = __expf(acc[nt][half * 2 + 1] * 0.125f - M) * inv;
                int colP = wnq + nt * 8 + (lane & 3) * 2;
                st_cs_f2(&attn[((size_t)bh * SS + i0 + row_l) * SS + j0 + colP], p0, p1);
                acc[nt][half * 2 + 0] = p0;
                acc[nt][half * 2 + 1] = p1;
            }
        }
        // pack P fragments
#pragma unroll
        for (int c = 0; c < 2; c++) {
            const int t0 = 2 * c, t1 = 2 * c + 1;
            float p00 = acc[t0][0], p01 = acc[t0][1], p02 = acc[t0][2], p03 = acc[t0][3];
            float p10 = acc[t1][0], p11 = acc[t1][1], p12 = acc[t1][2], p13 = acc[t1][3];
            __nv_bfloat16 h00 = __float2bfloat16(p00), h01 = __float2bfloat16(p01);
            __nv_bfloat16 h02 = __float2bfloat16(p02), h03 = __float2bfloat16(p03);
            __nv_bfloat16 h10 = __float2bfloat16(p10), h11 = __float2bfloat16(p11);
            __nv_bfloat16 h12 = __float2bfloat16(p12), h13 = __float2bfloat16(p13);
            Phi[c][0] = packhalves(h00, h01);
            Phi[c][1] = packhalves(h02, h03);
            Phi[c][2] = packhalves(h10, h11);
            Phi[c][3] = packhalves(h12, h13);
            Plo[c][0] = pack2bf(p00 - __bfloat162float(h00), p01 - __bfloat162float(h01));
            Plo[c][1] = pack2bf(p02 - __bfloat162float(h02), p03 - __bfloat162float(h03));
            Plo[c][2] = pack2bf(p10 - __bfloat162float(h10), p11 - __bfloat162float(h11));
            Plo[c][3] = pack2bf(p12 - __bfloat162float(h12), p13 - __bfloat162float(h13));
        }

        // AV: accv += P(m16 x j32) @ V(j32 x d64)
#pragma unroll
        for (int c = 0; c < 2; c++) {
            const int kcol = wnq + c * 16;
            uint32_t vhF[4][4], vlF[4][4];
#pragma unroll
            for (int dt = 0; dt < 4; dt++) {
                uint32_t bd = vb + (uint32_t)((dt * 16 + brow) * FA_ROW + (kcol + bkk0) * 2);
                ldsm_x4(vhF[dt], bd);
                ldsm_x4(vlF[dt], bd + FA_ARR);
            }
#pragma unroll
            for (int dn = 0; dn < 8; dn++) {
                const uint32_t* bhp = &vhF[dn >> 1][(dn & 1) * 2];
                const uint32_t* blp = &vlF[dn >> 1][(dn & 1) * 2];
                mma16816(accv[dn], Phi[c], bhp);
                mma16816(accv[dn], Phi[c], blp);
                mma16816(accv[dn], Plo[c], bhp);
            }
        }
        __syncthreads();
    }

    // Cross-jg reduce
    float* red = (float*)(smem + FA_KBASE);   // 16KB
    if (jg == 1) {
#pragma unroll
        for (int dn = 0; dn < 8; dn++)
#pragma unroll
            for (int half = 0; half < 2; half++) {
                int r = (lane >> 2) + half * 8;
                int d = dn * 8 + (lane & 3) * 2;
                *(float2*)&red[(mg * 16 + r) * 64 + d] =
                    make_float2(accv[dn][half * 2 + 0], accv[dn][half * 2 + 1]);
            }
    }
    __syncthreads();
    if (jg == 0) {
#pragma unroll
        for (int dn = 0; dn < 8; dn++)
#pragma unroll
            for (int half = 0; half < 2; half++) {
                int r = (lane >> 2) + half * 8;
                int d = dn * 8 + (lane & 3) * 2;
                float2 o = *(float2*)&red[(mg * 16 + r) * 64 + d];
                float x0 = accv[dn][half * 2 + 0] + o.x;
                float x1 = accv[dn][half * 2 + 1] + o.y;
                int s = i0 + wmq + r;
                size_t idx = ((size_t)b * SS + s) * DD + h * DKK + d;
                __nv_bfloat16 h0 = __float2bfloat16(x0);
                __nv_bfloat16 h1 = __float2bfloat16(x1);
                *(uint32_t*)&chi[idx] = packhalves(h0, h1);
                *(uint32_t*)&clo[idx] = pack2bf(x0 - __bfloat162float(h0),
                                                x1 - __bfloat162float(h1));
            }
    }
}

// ---------------------------------------------------------------------------
extern "C" void kernel_launch(void* const* d_in, const int* in_sizes, int n_in,
                              void* d_out, int out_size)
{
    const float* Q_in = (const float*)d_in[0];
    const float* K_in = (const float*)d_in[1];
    const float* V_in = (const float*)d_in[2];
    const float* Wq = (const float*)d_in[3];
    const float* bq = (const float*)d_in[4];
    const float* Wk = (const float*)d_in[5];
    const float* bk = (const float*)d_in[6];
    const float* Wv = (const float*)d_in[7];
    const float* bv = (const float*)d_in[8];
    const float* Wo = (const float*)d_in[9];
    const float* bo = (const float*)d_in[10];

    float* out = (float*)d_out;
    float* attn = out + OUT_ELEMS;

    void* p;
    cudaGetSymbolAddress(&p, g_qhi); __nv_bfloat16* qhi = (__nv_bfloat16*)p;
    cudaGetSymbolAddress(&p, g_qlo); __nv_bfloat16* qlo = (__nv_bfloat16*)p;
    cudaGetSymbolAddress(&p, g_khi); __nv_bfloat16* khi = (__nv_bfloat16*)p;
    cudaGetSymbolAddress(&p, g_klo); __nv_bfloat16* klo = (__nv_bfloat16*)p;
    cudaGetSymbolAddress(&p, g_vhi); __nv_bfloat16* vhi = (__nv_bfloat16*)p;
    cudaGetSymbolAddress(&p, g_vlo); __nv_bfloat16* vlo = (__nv_bfloat16*)p;
    cudaGetSymbolAddress(&p, g_vthi); __nv_bfloat16* vthi = (__nv_bfloat16*)p;
    cudaGetSymbolAddress(&p, g_vtlo); __nv_bfloat16* vtlo = (__nv_bfloat16*)p;
    cudaGetSymbolAddress(&p, g_chi); __nv_bfloat16* chi = (__nv_bfloat16*)p;
    cudaGetSymbolAddress(&p, g_clo); __nv_bfloat16* clo = (__nv_bfloat16*)p;
    cudaGetSymbolAddress(&p, g_Ahi); __nv_bfloat16* Ahi = (__nv_bfloat16*)p;
    cudaGetSymbolAddress(&p, g_Alo); __nv_bfloat16* Alo = (__nv_bfloat16*)p;
    cudaGetSymbolAddress(&p, g_Bhi); __nv_bfloat16* Bhi = (__nv_bfloat16*)p;
    cudaGetSymbolAddress(&p, g_Blo); __nv_bfloat16* Blo = (__nv_bfloat16*)p;

    cudaFuncSetAttribute(gemm_mma_kernel<0>, cudaFuncAttributeMaxDynamicSharedMemorySize, GM_SMEM_BYTES);
    cudaFuncSetAttribute(gemm_mma_kernel<1>, cudaFuncAttributeMaxDynamicSharedMemorySize, GM_SMEM_BYTES);
    cudaFuncSetAttribute(attn_fused_kernel, cudaFuncAttributeMaxDynamicSharedMemorySize, FA_SMEM);

    // 1. Batched conversions
    conv_qkv_kernel<<<3 * (int)(NELEM / 256), 256>>>(Q_in, K_in, V_in, Ahi, Alo);
    convT_all_kernel<<<4 * 256, 256>>>(Wq, Wk, Wv, Wo, Bhi, Blo);

    // 2. Batched QKV projection GEMM
    GemmOuts Pqkv;
    Pqkv.bias[0] = bq; Pqkv.bias[1] = bk; Pqkv.bias[2] = bv;
    Pqkv.hi[0] = qhi; Pqkv.hi[1] = khi; Pqkv.hi[2] = vhi;
    Pqkv.lo[0] = qlo; Pqkv.lo[1] = klo; Pqkv.lo[2] = vlo;
    Pqkv.cf[0] = Pqkv.cf[1] = Pqkv.cf[2] = nullptr;
    dim3 gemmGrid(DD / 128, (BB * SS) / 64, 3);
    gemm_mma_kernel<1><<<gemmGrid, 256, GM_SMEM_BYTES>>>(Ahi, Alo, Bhi, Blo, Pqkv);

    // 2b. V transpose [bh][s][d] -> [bh][d][s]
    dim3 vtGrid(SS / 64, BB * HH);
    vtrans_kernel<<<vtGrid, 256>>>(vhi, vlo, vthi, vtlo);

    // 3. Fused attention
    dim3 faGrid(SS / 64, BB * HH);
    attn_fused_kernel<<<faGrid, 256, FA_SMEM>>>(qhi, qlo, khi, klo, vthi, vtlo,
                                                attn, chi, clo);

    // 4. Output projection
    GemmOuts Po;
    Po.bias[0] = bo; Po.bias[1] = Po.bias[2] = nullptr;
    Po.cf[0] = out; Po.cf[1] = Po.cf[2] = nullptr;
    Po.hi[0] = Po.hi[1] = Po.hi[2] = nullptr;
    Po.lo[0] = Po.lo[1] = Po.lo[2] = nullptr;
    dim3 oGrid(DD / 128, (BB * SS) / 64, 1);
    gemm_mma_kernel<0><<<oGrid, 256, GM_SMEM_BYTES>>>(
        chi, clo, Bhi + 3 * (size_t)DD * DD, Blo + 3 * (size_t)DD * DD, Po);
}